// round 4
// baseline (speedup 1.0000x reference)
#include <cuda_runtime.h>
#include <mma.h>
#include <cstdint>
#include <cstddef>

using namespace nvcuda;

// ---------------- problem dims ----------------
#define NQ   4096
#define MKV  4096
#define RD   144
#define LD   3584
#define NH   4
#define HDIM 36
#define HPAD 40
#define VHD  896

// ---------------- scratch ----------------
__device__ __align__(16) float g_Q   [NQ * RD];
__device__ __align__(16) float g_K   [MKV * RD];
__device__ __align__(16) float g_Qp  [NH * NQ * HPAD];
__device__ __align__(16) float g_Kp  [NH * HPAD * MKV];
__device__ __align__(16) float g_Bv  [LD * LD];
__device__ __align__(16) float g_bv  [LD];
__device__ __align__(16) float g_V   [MKV * LD];
__device__ __align__(16) float g_S   [(size_t)NH * NQ * MKV];
__device__ __align__(16) float g_X   [NQ * LD];
__device__ __align__(16) float g_Y   [NQ * LD];

// ---------------- cp.async helpers ----------------
__device__ __forceinline__ uint32_t smem_u32(const void* p) {
    uint32_t a;
    asm("{ .reg .u64 t; cvta.to.shared.u64 t, %1; cvt.u32.u64 %0, t; }" : "=r"(a) : "l"(p));
    return a;
}
__device__ __forceinline__ void cp16(uint32_t dst, const void* src, int nbytes) {
    asm volatile("cp.async.cg.shared.global [%0], [%1], 16, %2;"
                 :: "r"(dst), "l"(src), "r"(nbytes) : "memory");
}
#define CP_COMMIT() asm volatile("cp.async.commit_group;" ::: "memory")
#define CP_WAIT(n)  asm volatile("cp.async.wait_group %0;" :: "n"(n) : "memory")

// ---------------- tf32 WMMA GEMM, BMTx128x32 tile, 4 warps ----------------
// C[M,N] = alpha * A[M,K] @ B[K,N] (+ bias[n]) (+ C if acc). Row-major.
// M % BMT == 0; N, K multiples of 4. Batched via blockIdx.z.
constexpr int BN = 128, BK = 32;
constexpr int LDAS = 36;               // A smem stride (floats): 2-way max conflict
constexpr int LDBS = 132;              // B smem stride (floats)
constexpr int BSTG = BK * LDBS;        // 4224 floats per B stage
constexpr int STAGES = 3;

constexpr int astg(int bmt)  { return bmt * LDAS; }
constexpr int smemb(int bmt) { return STAGES * (astg(bmt) + BSTG) * 4; }

template<int BMT>
__device__ __forceinline__ void load_stage(const float* __restrict__ A,
                                           const float* __restrict__ B,
                                           uint32_t sa, uint32_t sbb,
                                           int m0, int n0, int kbase,
                                           int N, int K, int lda, int ldb, int tid)
{
    // A tile: BMT rows x 32 floats (8 float4/row) -> BMT/16 f4 per thread.
#pragma unroll
    for (int i = 0; i < BMT / 16; i++) {
        int f = tid + i * 128;
        int r = f >> 3, c = f & 7;
        int gk = kbase + c * 4;
        const float* src = A + (size_t)(m0 + r) * lda + (gk < K ? gk : K - 4);
        int nb = (gk < K) ? 16 : 0;
        cp16(sa + (r * LDAS + c * 4) * 4, src, nb);
    }
    // B tile: 32 k-rows x 128 floats (32 f4/row) -> 8 per thread.
#pragma unroll
    for (int i = 0; i < 8; i++) {
        int f = tid + i * 128;
        int kr = f >> 5, c = f & 31;
        int gk = kbase + kr;
        int gn = n0 + c * 4;
        const float* src = B + (size_t)(gk < K ? gk : K - 1) * ldb + (gn < N ? gn : 0);
        int nb = (gk < K && gn < N) ? 16 : 0;
        cp16(sbb + (kr * LDBS + c * 4) * 4, src, nb);
    }
}

template<int BMT>
__global__ __launch_bounds__(128, 2)
void gemm_tf32(const float* __restrict__ A, const float* __restrict__ B,
               float* __restrict__ C, const float* __restrict__ bias,
               int M, int N, int K, int lda, int ldb, int ldc,
               long long sA, long long sB, long long sC,
               float alpha, int acc)
{
    constexpr int WM   = BMT / 2;      // warp m-extent
    constexpr int AI   = WM / 16;      // A frags per warp
    constexpr int ASTG = BMT * LDAS;

    extern __shared__ float smem[];
    float* As = smem;
    float* Bs = smem + STAGES * ASTG;
    const uint32_t sa_u = smem_u32(As);
    const uint32_t sb_u = smem_u32(Bs);

    const int tid  = threadIdx.x;
    const int warp = tid >> 5;
    const int wm   = warp & 1;    // 2 warp-rows
    const int wn   = warp >> 1;   // 2 warp-cols of 64
    const int m0   = blockIdx.y * BMT;
    const int n0   = blockIdx.x * BN;

    A += (size_t)blockIdx.z * sA;
    B += (size_t)blockIdx.z * sB;
    C += (size_t)blockIdx.z * sC;

    wmma::fragment<wmma::accumulator, 16, 16, 8, float> cf[AI][4];
#pragma unroll
    for (int i = 0; i < AI; i++)
#pragma unroll
        for (int j = 0; j < 4; j++)
            wmma::fill_fragment(cf[i][j], 0.f);

    const int KT = (K + BK - 1) / BK;

    // prologue: stages 0, 1
    load_stage<BMT>(A, B, sa_u, sb_u, m0, n0, 0, N, K, lda, ldb, tid);
    CP_COMMIT();
    if (KT > 1)
        load_stage<BMT>(A, B, sa_u + ASTG * 4, sb_u + BSTG * 4,
                        m0, n0, BK, N, K, lda, ldb, tid);
    CP_COMMIT();

    int cur = 0, nxt = 2;
#pragma unroll 1
    for (int kt = 0; kt < KT; kt++) {
        CP_WAIT(1);
        __syncthreads();

        const float* ap = As + cur * ASTG + wm * WM * LDAS;
        const float* bp = Bs + cur * BSTG + wn * 64;
#pragma unroll
        for (int ks = 0; ks < 4; ks++) {
            wmma::fragment<wmma::matrix_a, 16, 16, 8, wmma::precision::tf32, wmma::row_major> af[AI];
            wmma::fragment<wmma::matrix_b, 16, 16, 8, wmma::precision::tf32, wmma::row_major> bf[4];
#pragma unroll
            for (int i = 0; i < AI; i++)
                wmma::load_matrix_sync(af[i], ap + (i * 16) * LDAS + ks * 8, LDAS);
#pragma unroll
            for (int j = 0; j < 4; j++)
                wmma::load_matrix_sync(bf[j], bp + (ks * 8) * LDBS + j * 16, LDBS);
#pragma unroll
            for (int i = 0; i < AI; i++)
#pragma unroll
                for (int j = 0; j < 4; j++)
                    wmma::mma_sync(cf[i][j], af[i], bf[j], cf[i][j]);
        }

        // load stage kt+2 into buffer nxt (== (kt-1)%3; safe: bar above ordered
        // all reads of that buffer, MMA above only touches buffer cur)
        int t = kt + 2;
        if (t < KT)
            load_stage<BMT>(A, B, sa_u + nxt * ASTG * 4, sb_u + nxt * BSTG * 4,
                            m0, n0, t * BK, N, K, lda, ldb, tid);
        CP_COMMIT();

        cur = (cur == 2) ? 0 : cur + 1;
        nxt = (nxt == 2) ? 0 : nxt + 1;
    }

    __syncthreads();   // last MMA's smem reads done before Cs reuse

    // epilogue: stage C in smem, coalesced guarded float4 stores
    float* Cs = smem;  // BMT x LDBS floats, fits inside pipeline smem
#pragma unroll
    for (int i = 0; i < AI; i++)
#pragma unroll
        for (int j = 0; j < 4; j++)
            wmma::store_matrix_sync(Cs + (wm * WM + i * 16) * LDBS + wn * 64 + j * 16,
                                    cf[i][j], LDBS, wmma::mem_row_major);
    __syncthreads();

#pragma unroll 1
    for (int e = tid; e < BMT * 32; e += 128) {
        int rr = e >> 5, c4 = (e & 31) << 2;
        int gm = m0 + rr, gn = n0 + c4;
        if (gn >= N) continue;
        float4 v = *reinterpret_cast<float4*>(&Cs[rr * LDBS + c4]);
        v.x *= alpha; v.y *= alpha; v.z *= alpha; v.w *= alpha;
        if (bias) {
            float4 bv = *reinterpret_cast<const float4*>(bias + gn);
            v.x += bv.x; v.y += bv.y; v.z += bv.z; v.w += bv.w;
        }
        float* cp = C + (size_t)gm * ldc + gn;
        if (acc) {
            float4 o = *reinterpret_cast<float4*>(cp);
            v.x += o.x; v.y += o.y; v.z += o.z; v.w += o.w;
        }
        *reinterpret_cast<float4*>(cp) = v;
    }
}

// ---------------- repack: stacked per-head V weights -> [3584,3584] ----------------
__global__ void pack_v_k(const float* __restrict__ wv, const float* __restrict__ wvb,
                         float* __restrict__ Bv, float* __restrict__ bv)
{
    int idx = blockIdx.x * 256 + threadIdx.x;
    if (idx >= LD * LD) return;
    int k = idx / LD, n = idx % LD;
    int h = n / VHD, d = n % VHD;
    Bv[idx] = wv[((size_t)h * LD + k) * VHD + d];
    if (k == 0) bv[n] = wvb[h * VHD + d];
}

// ---------------- pad head dim 36->40; build Q [h][n][40] and K^T [h][40][m] ----------------
__global__ void pad_qk_k(const float* __restrict__ Q, const float* __restrict__ Ks,
                         float* __restrict__ Qp, float* __restrict__ Kp)
{
    int idx = blockIdx.x * 256 + threadIdx.x;
    if (idx >= NH * NQ * HPAD) return;
    int k = idx % HPAD;
    int n = (idx / HPAD) % NQ;
    int h = idx / (HPAD * NQ);
    float q = 0.f, kk = 0.f;
    if (k < HDIM) {
        q  = Q [n * RD + h * HDIM + k];
        kk = Ks[n * RD + h * HDIM + k];
    }
    Qp[idx] = q;
    Kp[((size_t)h * HPAD + k) * MKV + n] = kk;
}

// ---------------- row softmax over 4096, in place ----------------
__global__ void softmax_k(float* __restrict__ S)
{
    const int row = blockIdx.x;
    const int h   = blockIdx.y;
    float* p = S + ((size_t)(h * NQ + row)) * MKV;
    const int tid = threadIdx.x;

    float x[16];
#pragma unroll
    for (int i = 0; i < 16; i++) x[i] = p[tid + (i << 8)];

    float mx = -1e30f;
#pragma unroll
    for (int i = 0; i < 16; i++) mx = fmaxf(mx, x[i]);
#pragma unroll
    for (int o = 16; o > 0; o >>= 1) mx = fmaxf(mx, __shfl_xor_sync(0xffffffffu, mx, o));
    __shared__ float rmax[8], rsum[8];
    if ((tid & 31) == 0) rmax[tid >> 5] = mx;
    __syncthreads();
    mx = rmax[0];
#pragma unroll
    for (int i = 1; i < 8; i++) mx = fmaxf(mx, rmax[i]);

    float s = 0.f, e[16];
#pragma unroll
    for (int i = 0; i < 16; i++) { e[i] = __expf(x[i] - mx); s += e[i]; }
#pragma unroll
    for (int o = 16; o > 0; o >>= 1) s += __shfl_xor_sync(0xffffffffu, s, o);
    if ((tid & 31) == 0) rsum[tid >> 5] = s;
    __syncthreads();
    s = rsum[0];
#pragma unroll
    for (int i = 1; i < 8; i++) s += rsum[i];

    const float inv = 1.f / s;
#pragma unroll
    for (int i = 0; i < 16; i++) p[tid + (i << 8)] = e[i] * inv;
}

// ---------------- LayerNorm over 3584 ----------------
__global__ void ln_k(const float* __restrict__ X, float* __restrict__ Y,
                     const float* __restrict__ g, const float* __restrict__ b)
{
    const int row = blockIdx.x;
    const float* xr = X + (size_t)row * LD;
    float*       yr = Y + (size_t)row * LD;
    const int tid = threadIdx.x;

    float x[14];
#pragma unroll
    for (int i = 0; i < 14; i++) x[i] = xr[tid + (i << 8)];

    float s = 0.f;
#pragma unroll
    for (int i = 0; i < 14; i++) s += x[i];
#pragma unroll
    for (int o = 16; o > 0; o >>= 1) s += __shfl_xor_sync(0xffffffffu, s, o);
    __shared__ float r1[8], r2[8];
    if ((tid & 31) == 0) r1[tid >> 5] = s;
    __syncthreads();
    s = 0.f;
#pragma unroll
    for (int i = 0; i < 8; i++) s += r1[i];
    const float mu = s * (1.f / LD);

    float vs = 0.f;
#pragma unroll
    for (int i = 0; i < 14; i++) { float d = x[i] - mu; vs += d * d; }
#pragma unroll
    for (int o = 16; o > 0; o >>= 1) vs += __shfl_xor_sync(0xffffffffu, vs, o);
    if ((tid & 31) == 0) r2[tid >> 5] = vs;
    __syncthreads();
    vs = 0.f;
#pragma unroll
    for (int i = 0; i < 8; i++) vs += r2[i];
    const float inv = rsqrtf(vs * (1.f / LD) + 1e-5f);

#pragma unroll
    for (int i = 0; i < 14; i++) {
        int c = tid + (i << 8);
        yr[c] = (x[i] - mu) * inv * g[c] + b[c];
    }
}

// ---------------- host launcher ----------------
template<int BMT>
static inline void launch_gemm(const float* A, const float* B, float* C, const float* bias,
                               int M, int N, int K, int lda, int ldb, int ldc,
                               long long sA, long long sB, long long sC, int batch,
                               float alpha, int acc)
{
    dim3 grid((N + BN - 1) / BN, M / BMT, batch);
    gemm_tf32<BMT><<<grid, 128, smemb(BMT)>>>(A, B, C, bias, M, N, K, lda, ldb, ldc,
                                              sA, sB, sC, alpha, acc);
}

extern "C" void kernel_launch(void* const* d_in, const int* in_sizes, int n_in,
                              void* d_out, int out_size)
{
    (void)in_sizes; (void)n_in; (void)out_size;
    const float* target  = (const float*)d_in[0];
    const float* source  = (const float*)d_in[1];
    const float* value   = (const float*)d_in[2];
    const float* wq_w    = (const float*)d_in[3];
    const float* wq_b    = (const float*)d_in[4];
    const float* wk_w    = (const float*)d_in[5];
    const float* wk_b    = (const float*)d_in[6];
    const float* wv_w    = (const float*)d_in[7];
    const float* wv_b    = (const float*)d_in[8];
    const float* resid_w = (const float*)d_in[9];
    const float* resid_b = (const float*)d_in[10];
    const float* out_w   = (const float*)d_in[11];
    const float* out_b   = (const float*)d_in[12];
    const float* ln_g    = (const float*)d_in[13];
    const float* ln_b    = (const float*)d_in[14];
    float* out = (float*)d_out;

    cudaFuncSetAttribute((const void*)gemm_tf32<128>,
                         cudaFuncAttributeMaxDynamicSharedMemorySize, smemb(128));
    cudaFuncSetAttribute((const void*)gemm_tf32<64>,
                         cudaFuncAttributeMaxDynamicSharedMemorySize, smemb(64));

    float *pQ, *pK, *pQp, *pKp, *pBv, *pbv, *pV, *pS, *pX, *pY;
    cudaGetSymbolAddress((void**)&pQ,  g_Q);
    cudaGetSymbolAddress((void**)&pK,  g_K);
    cudaGetSymbolAddress((void**)&pQp, g_Qp);
    cudaGetSymbolAddress((void**)&pKp, g_Kp);
    cudaGetSymbolAddress((void**)&pBv, g_Bv);
    cudaGetSymbolAddress((void**)&pbv, g_bv);
    cudaGetSymbolAddress((void**)&pV,  g_V);
    cudaGetSymbolAddress((void**)&pS,  g_S);
    cudaGetSymbolAddress((void**)&pX,  g_X);
    cudaGetSymbolAddress((void**)&pY,  g_Y);

    // 1) pack per-head V weights
    pack_v_k<<<(LD * LD + 255) / 256, 256>>>(wv_w, wv_b, pBv, pbv);

    // 2) Q = target @ wq_w + wq_b          [4096,144]   (narrow N -> BM=64 grid fill)
    launch_gemm<64>(target, wq_w, pQ, wq_b, NQ, RD, RD, RD, RD, RD, 0, 0, 0, 1, 1.f, 0);

    // 3) K = source @ wk_w + wk_b          [4096,144]
    launch_gemm<64>(source, wk_w, pK, wk_b, MKV, RD, LD, LD, RD, RD, 0, 0, 0, 1, 1.f, 0);

    // 4) pad + transpose per head
    pad_qk_k<<<(NH * NQ * HPAD + 255) / 256, 256>>>(pQ, pK, pQp, pKp);

    // 5) scores[h] = (Qp[h] @ Kp[h]) / 6   [4][4096][4096]
    launch_gemm<128>(pQp, pKp, pS, nullptr, NQ, MKV, HPAD,
                     HPAD, MKV, MKV,
                     (long long)NQ * HPAD, (long long)HPAD * MKV, (long long)NQ * MKV,
                     NH, 1.f / 6.f, 0);

    // 6) softmax rows (in place)
    softmax_k<<<dim3(NQ, NH), 256>>>(pS);

    // 7) V = value @ Bv + bv               [4096,3584]
    launch_gemm<128>(value, pBv, pV, pbv, MKV, LD, LD, LD, LD, LD, 0, 0, 0, 1, 1.f, 0);

    // 8) ctx[h] = P[h] @ V[:, h*896:(h+1)*896]
    launch_gemm<128>(pS, pV, pX, nullptr, NQ, VHD, MKV,
                     MKV, LD, LD,
                     (long long)NQ * MKV, (long long)VHD, (long long)VHD,
                     NH, 1.f, 0);

    // 9) X += target @ resid_w + resid_b
    launch_gemm<128>(target, resid_w, pX, resid_b, NQ, LD, RD, RD, LD, LD, 0, 0, 0, 1, 1.f, 1);

    // 10) LayerNorm
    ln_k<<<NQ, 256>>>(pX, pY, ln_g, ln_b);

    // 11) out = Y @ out_w + out_b
    launch_gemm<128>(pY, out_w, out, out_b, NQ, LD, LD, LD, LD, LD, 0, 0, 0, 1, 1.f, 0);
}

// round 5
// speedup vs baseline: 3.8441x; 3.8441x over previous
#include <cuda_runtime.h>
#include <cuda_fp16.h>
#include <mma.h>
#include <cstdint>
#include <cstddef>

using namespace nvcuda;

// ---------------- problem dims ----------------
#define NQ   4096
#define MKV  4096
#define RD   144
#define LD   3584
#define NH   4
#define HDIM 36
#define HPAD 40
#define VHD  896

// ---------------- scratch ----------------
__device__ __align__(16) __half g_th  [NQ * RD];           // target fp16
__device__ __align__(16) __half g_srch[MKV * LD];          // source fp16
__device__ __align__(16) __half g_valh[MKV * LD];          // value fp16
__device__ __align__(16) __half g_wqh [RD * RD];
__device__ __align__(16) __half g_wkh [LD * RD];
__device__ __align__(16) __half g_resh[RD * LD];
__device__ __align__(16) __half g_outh[LD * LD];
__device__ __align__(16) __half g_Bvh [LD * LD];           // packed wv fp16
__device__ __align__(16) float  g_bv  [LD];
__device__ __align__(16) float  g_Q   [NQ * RD];
__device__ __align__(16) float  g_K   [MKV * RD];
__device__ __align__(16) __half g_Qp  [NH * NQ * HPAD];
__device__ __align__(16) __half g_Kp  [NH * HPAD * MKV];
__device__ __align__(16) __half g_Sh  [(size_t)NH * NQ * MKV];  // scores/probs fp16
__device__ __align__(16) __half g_Vh  [MKV * LD];          // projected V fp16
__device__ __align__(16) float  g_X   [NQ * LD];
__device__ __align__(16) __half g_Yh  [NQ * LD];

// ---------------- cp.async helpers ----------------
__device__ __forceinline__ uint32_t smem_u32(const void* p) {
    uint32_t a;
    asm("{ .reg .u64 t; cvta.to.shared.u64 t, %1; cvt.u32.u64 %0, t; }" : "=r"(a) : "l"(p));
    return a;
}
__device__ __forceinline__ void cp16(uint32_t dst, const void* src, int nbytes) {
    asm volatile("cp.async.cg.shared.global [%0], [%1], 16, %2;"
                 :: "r"(dst), "l"(src), "r"(nbytes) : "memory");
}
#define CP_COMMIT() asm volatile("cp.async.commit_group;" ::: "memory")
#define CP_WAIT(n)  asm volatile("cp.async.wait_group %0;" :: "n"(n) : "memory")

// ---------------- fp16 WMMA GEMM (fp32 accumulate), BMTx128x32, 4 warps ----------------
// C[M,N] = alpha * A[M,K] @ B[K,N] (+ bias[n]) (+ C if acc, fp32 out only).
// A, B fp16 row-major. Output fp32 (outhalf=0) or fp16 (outhalf=1).
// M % BMT == 0; N % 8 == 0; K arbitrary (zfill). Batched via blockIdx.z.
constexpr int BN = 128, BK = 32;
constexpr int LDAS = 40;               // halfs; 80B/row -> conflict-free LDSM
constexpr int LDBS = 136;              // halfs; 272B/row -> conflict-free LDSM
constexpr int BSTG = BK * LDBS;        // 4352 halfs per B stage
constexpr int STAGES = 3;

constexpr int astg_h(int bmt) { return bmt * LDAS; }
constexpr int smemb(int bmt) {
    int pipe = STAGES * (astg_h(bmt) + BSTG) * 2;
    int cs   = bmt * 132 * 4;
    return pipe > cs ? pipe : cs;
}

template<int BMT>
__device__ __forceinline__ void load_stage(const __half* __restrict__ A,
                                           const __half* __restrict__ B,
                                           uint32_t sa, uint32_t sbb,
                                           int m0, int n0, int kbase,
                                           int N, int K, int lda, int ldb, int tid)
{
    // A tile: BMT rows x 32 halfs (4 chunks of 8). BMT*4/128 per thread.
#pragma unroll
    for (int i = 0; i < BMT / 32; i++) {
        int f = tid + i * 128;
        int r = f >> 2, c = f & 3;
        int gk = kbase + c * 8;
        const __half* src = A + (size_t)(m0 + r) * lda + (gk < K ? gk : 0);
        int nb = (gk < K) ? 16 : 0;
        cp16(sa + (r * LDAS + c * 8) * 2, src, nb);
    }
    // B tile: 32 k-rows x 128 halfs (16 chunks of 8). 4 per thread.
#pragma unroll
    for (int i = 0; i < 4; i++) {
        int f = tid + i * 128;
        int kr = f >> 4, c = f & 15;
        int gk = kbase + kr;
        int gn = n0 + c * 8;
        const __half* src = B + (size_t)(gk < K ? gk : K - 1) * ldb + (gn < N ? gn : 0);
        int nb = (gk < K && gn < N) ? 16 : 0;
        cp16(sbb + (kr * LDBS + c * 8) * 2, src, nb);
    }
}

template<int BMT>
__global__ __launch_bounds__(128, 2)
void gemm_h(const __half* __restrict__ A, const __half* __restrict__ B,
            void* __restrict__ Cv, const float* __restrict__ bias,
            int M, int N, int K, int lda, int ldb, int ldc,
            long long sA, long long sB, long long sC,
            float alpha, int acc, int outhalf)
{
    constexpr int WM   = BMT / 2;
    constexpr int AI   = WM / 16;
    constexpr int ASTG = BMT * LDAS;

    extern __shared__ char smem_raw[];
    __half* As = (__half*)smem_raw;
    __half* Bs = As + STAGES * ASTG;
    const uint32_t sa_u = smem_u32(As);
    const uint32_t sb_u = smem_u32(Bs);

    const int tid  = threadIdx.x;
    const int warp = tid >> 5;
    const int wm   = warp & 1;
    const int wn   = warp >> 1;
    const int m0   = blockIdx.y * BMT;
    const int n0   = blockIdx.x * BN;

    A += (size_t)blockIdx.z * sA;
    B += (size_t)blockIdx.z * sB;
    float*  Cf = (float*)Cv  + (size_t)blockIdx.z * sC;
    __half* Ch = (__half*)Cv + (size_t)blockIdx.z * sC;

    wmma::fragment<wmma::accumulator, 16, 16, 16, float> cf[AI][4];
#pragma unroll
    for (int i = 0; i < AI; i++)
#pragma unroll
        for (int j = 0; j < 4; j++)
            wmma::fill_fragment(cf[i][j], 0.f);

    const int KT = (K + BK - 1) / BK;

    load_stage<BMT>(A, B, sa_u, sb_u, m0, n0, 0, N, K, lda, ldb, tid);
    CP_COMMIT();
    if (KT > 1)
        load_stage<BMT>(A, B, sa_u + ASTG * 2, sb_u + BSTG * 2,
                        m0, n0, BK, N, K, lda, ldb, tid);
    CP_COMMIT();

    int cur = 0, nxt = 2;
#pragma unroll 1
    for (int kt = 0; kt < KT; kt++) {
        CP_WAIT(1);
        __syncthreads();

        const __half* ap = As + cur * ASTG + wm * WM * LDAS;
        const __half* bp = Bs + cur * BSTG + wn * 64;
#pragma unroll
        for (int ks = 0; ks < 2; ks++) {
            wmma::fragment<wmma::matrix_a, 16, 16, 16, __half, wmma::row_major> af[AI];
            wmma::fragment<wmma::matrix_b, 16, 16, 16, __half, wmma::row_major> bf[4];
#pragma unroll
            for (int i = 0; i < AI; i++)
                wmma::load_matrix_sync(af[i], ap + (i * 16) * LDAS + ks * 16, LDAS);
#pragma unroll
            for (int j = 0; j < 4; j++)
                wmma::load_matrix_sync(bf[j], bp + (ks * 16) * LDBS + j * 16, LDBS);
#pragma unroll
            for (int i = 0; i < AI; i++)
#pragma unroll
                for (int j = 0; j < 4; j++)
                    wmma::mma_sync(cf[i][j], af[i], bf[j], cf[i][j]);
        }

        int t = kt + 2;
        if (t < KT)
            load_stage<BMT>(A, B, sa_u + nxt * ASTG * 2, sb_u + nxt * BSTG * 2,
                            m0, n0, t * BK, N, K, lda, ldb, tid);
        CP_COMMIT();

        cur = (cur == 2) ? 0 : cur + 1;
        nxt = (nxt == 2) ? 0 : nxt + 1;
    }

    __syncthreads();

    // epilogue via fp32 smem staging
    float* Cs = (float*)smem_raw;   // BMT x 132 floats
#pragma unroll
    for (int i = 0; i < AI; i++)
#pragma unroll
        for (int j = 0; j < 4; j++)
            wmma::store_matrix_sync(Cs + (wm * WM + i * 16) * 132 + wn * 64 + j * 16,
                                    cf[i][j], 132, wmma::mem_row_major);
    __syncthreads();

#pragma unroll 1
    for (int e = tid; e < BMT * 32; e += 128) {
        int rr = e >> 5, c4 = (e & 31) << 2;
        int gm = m0 + rr, gn = n0 + c4;
        if (gn >= N) continue;
        float4 v = *reinterpret_cast<float4*>(&Cs[rr * 132 + c4]);
        v.x *= alpha; v.y *= alpha; v.z *= alpha; v.w *= alpha;
        if (bias) {
            float4 bv = *reinterpret_cast<const float4*>(bias + gn);
            v.x += bv.x; v.y += bv.y; v.z += bv.z; v.w += bv.w;
        }
        if (outhalf) {
            __half* cp = Ch + (size_t)gm * ldc + gn;
            __half2 h0 = __floats2half2_rn(v.x, v.y);
            __half2 h1 = __floats2half2_rn(v.z, v.w);
            *reinterpret_cast<__half2*>(cp)     = h0;
            *reinterpret_cast<__half2*>(cp + 2) = h1;
        } else {
            float* cp = Cf + (size_t)gm * ldc + gn;
            if (acc) {
                float4 o = *reinterpret_cast<float4*>(cp);
                v.x += o.x; v.y += o.y; v.z += o.z; v.w += o.w;
            }
            *reinterpret_cast<float4*>(cp) = v;
        }
    }
}

// ---------------- fp32 -> fp16 convert (n % 4 == 0) ----------------
__global__ void f2h_k(const float* __restrict__ in, __half* __restrict__ out, int n)
{
    int i = (blockIdx.x * 256 + threadIdx.x) * 4;
    if (i >= n) return;
    float4 v = *reinterpret_cast<const float4*>(in + i);
    *reinterpret_cast<__half2*>(out + i)     = __floats2half2_rn(v.x, v.y);
    *reinterpret_cast<__half2*>(out + i + 2) = __floats2half2_rn(v.z, v.w);
}

// ---------------- repack per-head V weights -> fp16 [3584,3584], bias fp32 ----------------
__global__ void pack_v_k(const float* __restrict__ wv, const float* __restrict__ wvb,
                         __half* __restrict__ Bv, float* __restrict__ bv)
{
    int idx = blockIdx.x * 256 + threadIdx.x;
    if (idx >= LD * LD) return;
    int k = idx / LD, n = idx % LD;
    int h = n / VHD, d = n % VHD;
    Bv[idx] = __float2half_rn(wv[((size_t)h * LD + k) * VHD + d]);
    if (k == 0) bv[n] = wvb[h * VHD + d];
}

// ---------------- pad head dim 36->40 (fp16): Q [h][n][40], K^T [h][40][m] ----------------
__global__ void pad_qk_k(const float* __restrict__ Q, const float* __restrict__ Ks,
                         __half* __restrict__ Qp, __half* __restrict__ Kp)
{
    int idx = blockIdx.x * 256 + threadIdx.x;
    if (idx >= NH * NQ * HPAD) return;
    int k = idx % HPAD;
    int n = (idx / HPAD) % NQ;
    int h = idx / (HPAD * NQ);
    float q = 0.f, kk = 0.f;
    if (k < HDIM) {
        q  = Q [n * RD + h * HDIM + k];
        kk = Ks[n * RD + h * HDIM + k];
    }
    Qp[idx] = __float2half_rn(q);
    Kp[((size_t)h * HPAD + k) * MKV + n] = __float2half_rn(kk);
}

// ---------------- row softmax over 4096 fp16, in place ----------------
__global__ void softmax_h(__half* __restrict__ S)
{
    const int row = blockIdx.x;
    const int h   = blockIdx.y;
    __half2* p = reinterpret_cast<__half2*>(S + ((size_t)(h * NQ + row)) * MKV);
    const int tid = threadIdx.x;   // 256 threads, 2048 half2 -> 8 each

    float2 x[8];
#pragma unroll
    for (int i = 0; i < 8; i++) x[i] = __half22float2(p[tid + (i << 8)]);

    float mx = -1e30f;
#pragma unroll
    for (int i = 0; i < 8; i++) mx = fmaxf(mx, fmaxf(x[i].x, x[i].y));
#pragma unroll
    for (int o = 16; o > 0; o >>= 1) mx = fmaxf(mx, __shfl_xor_sync(0xffffffffu, mx, o));
    __shared__ float rmax[8], rsum[8];
    if ((tid & 31) == 0) rmax[tid >> 5] = mx;
    __syncthreads();
    mx = rmax[0];
#pragma unroll
    for (int i = 1; i < 8; i++) mx = fmaxf(mx, rmax[i]);

    float s = 0.f;
    float2 e[8];
#pragma unroll
    for (int i = 0; i < 8; i++) {
        e[i].x = __expf(x[i].x - mx);
        e[i].y = __expf(x[i].y - mx);
        s += e[i].x + e[i].y;
    }
#pragma unroll
    for (int o = 16; o > 0; o >>= 1) s += __shfl_xor_sync(0xffffffffu, s, o);
    if ((tid & 31) == 0) rsum[tid >> 5] = s;
    __syncthreads();
    s = rsum[0];
#pragma unroll
    for (int i = 1; i < 8; i++) s += rsum[i];

    const float inv = 1.f / s;
#pragma unroll
    for (int i = 0; i < 8; i++)
        p[tid + (i << 8)] = __floats2half2_rn(e[i].x * inv, e[i].y * inv);
}

// ---------------- LayerNorm over 3584, fp32 in -> fp16 out ----------------
__global__ void ln_k(const float* __restrict__ X, __half* __restrict__ Y,
                     const float* __restrict__ g, const float* __restrict__ b)
{
    const int row = blockIdx.x;
    const float* xr = X + (size_t)row * LD;
    __half*      yr = Y + (size_t)row * LD;
    const int tid = threadIdx.x;

    float x[14];
#pragma unroll
    for (int i = 0; i < 14; i++) x[i] = xr[tid + (i << 8)];

    float s = 0.f;
#pragma unroll
    for (int i = 0; i < 14; i++) s += x[i];
#pragma unroll
    for (int o = 16; o > 0; o >>= 1) s += __shfl_xor_sync(0xffffffffu, s, o);
    __shared__ float r1[8], r2[8];
    if ((tid & 31) == 0) r1[tid >> 5] = s;
    __syncthreads();
    s = 0.f;
#pragma unroll
    for (int i = 0; i < 8; i++) s += r1[i];
    const float mu = s * (1.f / LD);

    float vs = 0.f;
#pragma unroll
    for (int i = 0; i < 14; i++) { float d = x[i] - mu; vs += d * d; }
#pragma unroll
    for (int o = 16; o > 0; o >>= 1) vs += __shfl_xor_sync(0xffffffffu, vs, o);
    if ((tid & 31) == 0) r2[tid >> 5] = vs;
    __syncthreads();
    vs = 0.f;
#pragma unroll
    for (int i = 0; i < 8; i++) vs += r2[i];
    const float inv = rsqrtf(vs * (1.f / LD) + 1e-5f);

#pragma unroll
    for (int i = 0; i < 14; i++) {
        int c = tid + (i << 8);
        yr[c] = __float2half_rn((x[i] - mu) * inv * g[c] + b[c]);
    }
}

// ---------------- host launcher ----------------
template<int BMT>
static inline void launch_gemm(const __half* A, const __half* B, void* C, const float* bias,
                               int M, int N, int K, int lda, int ldb, int ldc,
                               long long sA, long long sB, long long sC, int batch,
                               float alpha, int acc, int outhalf)
{
    dim3 grid((N + BN - 1) / BN, M / BMT, batch);
    gemm_h<BMT><<<grid, 128, smemb(BMT)>>>(A, B, C, bias, M, N, K, lda, ldb, ldc,
                                           sA, sB, sC, alpha, acc, outhalf);
}

static inline void f2h(const float* in, __half* out, int n)
{
    f2h_k<<<(n / 4 + 255) / 256, 256>>>(in, out, n);
}

extern "C" void kernel_launch(void* const* d_in, const int* in_sizes, int n_in,
                              void* d_out, int out_size)
{
    (void)in_sizes; (void)n_in; (void)out_size;
    const float* target  = (const float*)d_in[0];
    const float* source  = (const float*)d_in[1];
    const float* value   = (const float*)d_in[2];
    const float* wq_w    = (const float*)d_in[3];
    const float* wq_b    = (const float*)d_in[4];
    const float* wk_w    = (const float*)d_in[5];
    const float* wk_b    = (const float*)d_in[6];
    const float* wv_w    = (const float*)d_in[7];
    const float* wv_b    = (const float*)d_in[8];
    const float* resid_w = (const float*)d_in[9];
    const float* resid_b = (const float*)d_in[10];
    const float* out_w   = (const float*)d_in[11];
    const float* out_b   = (const float*)d_in[12];
    const float* ln_g    = (const float*)d_in[13];
    const float* ln_b    = (const float*)d_in[14];
    float* out = (float*)d_out;

    cudaFuncSetAttribute((const void*)gemm_h<128>,
                         cudaFuncAttributeMaxDynamicSharedMemorySize, smemb(128));
    cudaFuncSetAttribute((const void*)gemm_h<64>,
                         cudaFuncAttributeMaxDynamicSharedMemorySize, smemb(64));

    __half *pth, *psrch, *pvalh, *pwqh, *pwkh, *presh, *pouth, *pBvh, *pQp, *pKp, *pSh, *pVh, *pYh;
    float *pbv, *pQ, *pK, *pX;
    cudaGetSymbolAddress((void**)&pth,   g_th);
    cudaGetSymbolAddress((void**)&psrch, g_srch);
    cudaGetSymbolAddress((void**)&pvalh, g_valh);
    cudaGetSymbolAddress((void**)&pwqh,  g_wqh);
    cudaGetSymbolAddress((void**)&pwkh,  g_wkh);
    cudaGetSymbolAddress((void**)&presh, g_resh);
    cudaGetSymbolAddress((void**)&pouth, g_outh);
    cudaGetSymbolAddress((void**)&pBvh,  g_Bvh);
    cudaGetSymbolAddress((void**)&pbv,   g_bv);
    cudaGetSymbolAddress((void**)&pQ,    g_Q);
    cudaGetSymbolAddress((void**)&pK,    g_K);
    cudaGetSymbolAddress((void**)&pQp,   g_Qp);
    cudaGetSymbolAddress((void**)&pKp,   g_Kp);
    cudaGetSymbolAddress((void**)&pSh,   g_Sh);
    cudaGetSymbolAddress((void**)&pVh,   g_Vh);
    cudaGetSymbolAddress((void**)&pX,    g_X);
    cudaGetSymbolAddress((void**)&pYh,   g_Yh);

    // 0) fp32 -> fp16 conversions
    f2h(target,  pth,   NQ * RD);
    f2h(source,  psrch, MKV * LD);
    f2h(value,   pvalh, MKV * LD);
    f2h(wq_w,    pwqh,  RD * RD);
    f2h(wk_w,    pwkh,  LD * RD);
    f2h(resid_w, presh, RD * LD);
    f2h(out_w,   pouth, LD * LD);
    pack_v_k<<<(LD * LD + 255) / 256, 256>>>(wv_w, wv_b, pBvh, pbv);

    // 1) Q = target @ wq_w + wq_b         [4096,144] fp32
    launch_gemm<64>(pth, pwqh, pQ, wq_b, NQ, RD, RD, RD, RD, RD, 0, 0, 0, 1, 1.f, 0, 0);

    // 2) K = source @ wk_w + wk_b         [4096,144] fp32
    launch_gemm<64>(psrch, pwkh, pK, wk_b, MKV, RD, LD, LD, RD, RD, 0, 0, 0, 1, 1.f, 0, 0);

    // 3) pad + transpose per head (fp16 out)
    pad_qk_k<<<(NH * NQ * HPAD + 255) / 256, 256>>>(pQ, pK, pQp, pKp);

    // 4) scores[h] = (Qp[h] @ Kp[h]) / 6  -> fp16 S
    launch_gemm<128>(pQp, pKp, pSh, nullptr, NQ, MKV, HPAD,
                     HPAD, MKV, MKV,
                     (long long)NQ * HPAD, (long long)HPAD * MKV, (long long)NQ * MKV,
                     NH, 1.f / 6.f, 0, 1);

    // 5) softmax rows (fp16 in place)
    softmax_h<<<dim3(NQ, NH), 256>>>(pSh);

    // 6) V = value @ Bv + bv              -> fp16 [4096,3584]
    launch_gemm<128>(pvalh, pBvh, pVh, pbv, MKV, LD, LD, LD, LD, LD, 0, 0, 0, 1, 1.f, 0, 1);

    // 7) ctx[h] = P[h] @ V[:, h*896:(h+1)*896]  -> fp32 X columns
    launch_gemm<128>(pSh, pVh, pX, nullptr, NQ, VHD, MKV,
                     MKV, LD, LD,
                     (long long)NQ * MKV, (long long)VHD, (long long)VHD,
                     NH, 1.f, 0, 0);

    // 8) X += target @ resid_w + resid_b  (fp32 accumulate)
    launch_gemm<128>(pth, presh, pX, resid_b, NQ, LD, RD, RD, LD, LD, 0, 0, 0, 1, 1.f, 1, 0);

    // 9) LayerNorm -> fp16 Y
    ln_k<<<NQ, 256>>>(pX, pYh, ln_g, ln_b);

    // 10) out = Y @ out_w + out_b         -> fp32
    launch_gemm<128>(pYh, pouth, out, out_b, NQ, LD, LD, LD, LD, LD, 0, 0, 0, 1, 1.f, 0, 0);
}